// round 16
// baseline (speedup 1.0000x reference)
#include <cuda_runtime.h>
#include <cuda_bf16.h>

// SpatialConsistencyLoss — single launch, loss done as an EPILOGUE by the
// last quarter of producer blocks (no dedicated consumer blocks).
//   original, enhanced: [32,3,512,512] f32
//   p = avg_pool4(mean_c(orig)) - avg_pool4(mean_c(enh))   [32,128,128]
//   loss[i,j] = sum_dirs (p[i,j] - p[nbr])^2, zero-padded  -> [32,1,128,128]
//
// R14 diagnosis: dedicated consumer blocks spin resident through the stream
// -> ~20% of block slots idle -> stream rate 6.4 -> 5.6 TB/s. Fix: no
// consumer blocks at all. 2048 producers; block bid=1536+t additionally
// computes loss tile t (8 pooled rows, image t/16) after its own stream
// work. Readiness math: tile t's image is done after ~4t+64 producer
// completions; block 1536+t frees at ~1536+t completions; 4t+64 <= 1536+t
// for t<=490 -> only the last ~21 blocks (images 30-31) briefly spin.
// Loss traffic (+4MB) amortizes into the bandwidth-bound stream.
//
// Deadlock-free: <=512 waiters << ~1184-block capacity, and every block
// executes its production before any wait, so per-image counters always
// complete. Reset: the 512th tile completion implies every image counter
// reached 64 (all tiles waited on them), so the last tile-finisher can
// safely zero all counters -> graph-replay deterministic.

#define B 32
#define HP 128
#define WP 128
#define NPOOL (B * HP * WP)   // 524288
#define HIN 512
#define WIN 512
#define CH_STRIDE (HIN * WIN)          // 262144
#define IMG_STRIDE (3 * CH_STRIDE)     // 786432
#define THREADS 256
#define POOL_BLOCKS (NPOOL / THREADS)      // 2048 (64 per image)
#define LOSS_BLOCKS (NPOOL / 4 / THREADS)  // 512 tiles (16 per image)
#define TAIL_START (POOL_BLOCKS - LOSS_BLOCKS)  // 1536
#define PROD_PER_IMG (POOL_BLOCKS / B)     // 64

__device__ float g_pooled[NPOOL];            // 2 MB scratch
__device__ unsigned int g_img_done[B];       // per-image producer counters
__device__ unsigned int g_tiles_done;        // completed loss tiles (reset)

__device__ __forceinline__ float sq(float x) { return x * x; }

__global__ void scl_epilogue_kernel(const float* __restrict__ orig,
                                    const float* __restrict__ enh,
                                    float* __restrict__ out) {
    // ================= Production: every block streams 1/2048 =============
    int idx = blockIdx.x * THREADS + threadIdx.x;

    int j = idx & (WP - 1);
    int i = (idx >> 7) & (HP - 1);
    int b = idx >> 14;

    int base0 = b * IMG_STRIDE + (i * 4) * WIN + (j * 4);

    float s = 0.0f;
#pragma unroll
    for (int c = 0; c < 3; ++c) {
        int base = base0 + c * CH_STRIDE;
#pragma unroll
        for (int r = 0; r < 4; ++r) {
            float4 ov = __ldcs(reinterpret_cast<const float4*>(orig + base + r * WIN));
            float4 ev = __ldcs(reinterpret_cast<const float4*>(enh  + base + r * WIN));
            s += (ov.x - ev.x) + (ov.y - ev.y) + (ov.z - ev.z) + (ov.w - ev.w);
        }
    }
    g_pooled[idx] = s * (1.0f / 48.0f);   // /3 channels, /16 pool

    __syncthreads();
    if (threadIdx.x == 0) {
        __threadfence();                  // release this block's scratch
        atomicAdd(&g_img_done[b], 1u);
    }

    // ================= Epilogue: last 512 blocks each do one loss tile ====
    if (blockIdx.x >= TAIL_START) {
        int t   = blockIdx.x - TAIL_START;   // tile 0..511
        int img = t >> 4;                    // tile's image (rows 8t..8t+7)

        if (threadIdx.x == 0) {
            // Almost always already satisfied (see readiness math above).
            while (*(volatile unsigned int*)&g_img_done[img] < PROD_PER_IMG) { }
            __threadfence();                 // acquire that image's scratch
        }
        __syncthreads();

        int q   = t * THREADS + threadIdx.x; // quad index, 0 .. NPOOL/4-1
        int j4  = (q & 31) << 2;             // first j of the 4-wide quad
        int row = q >> 5;                    // b*128 + i (within image img)
        int ii  = row & (HP - 1);
        int base = (row << 7) + j4;

        const float4* p4 = reinterpret_cast<const float4*>(g_pooled);
        float4 c  = p4[base >> 2];
        float4 up = (ii > 0)      ? p4[(base - WP) >> 2] : make_float4(0.f, 0.f, 0.f, 0.f);
        float4 dn = (ii < HP - 1) ? p4[(base + WP) >> 2] : make_float4(0.f, 0.f, 0.f, 0.f);
        float left  = (j4 > 0)      ? g_pooled[base - 1] : 0.f;
        float right = (j4 < WP - 4) ? g_pooled[base + 4] : 0.f;

        float4 o;
        o.x = sq(c.x - left) + sq(c.x - c.y)   + sq(c.x - up.x) + sq(c.x - dn.x);
        o.y = sq(c.y - c.x)  + sq(c.y - c.z)   + sq(c.y - up.y) + sq(c.y - dn.y);
        o.z = sq(c.z - c.y)  + sq(c.z - c.w)   + sq(c.z - up.z) + sq(c.z - dn.z);
        o.w = sq(c.w - c.z)  + sq(c.w - right) + sq(c.w - up.w) + sq(c.w - dn.w);

        reinterpret_cast<float4*>(out)[base >> 2] = o;

        // -------- Reset shared state for the next graph replay --------
        __syncthreads();
        if (threadIdx.x == 0) {
            unsigned int old = atomicAdd(&g_tiles_done, 1u);
            if (old == LOSS_BLOCKS - 1) {    // last tile => all counters done
#pragma unroll
                for (int k = 0; k < B; ++k)
                    atomicExch(&g_img_done[k], 0u);
                atomicExch(&g_tiles_done, 0u);
            }
        }
    }
}

extern "C" void kernel_launch(void* const* d_in, const int* in_sizes, int n_in,
                              void* d_out, int out_size) {
    const float* orig = (const float*)d_in[0];
    const float* enh  = (const float*)d_in[1];
    float* out = (float*)d_out;

    scl_epilogue_kernel<<<POOL_BLOCKS, THREADS>>>(orig, enh, out);
}

// round 17
// speedup vs baseline: 1.0130x; 1.0130x over previous
#include <cuda_runtime.h>
#include <cuda_bf16.h>

// SpatialConsistencyLoss — single launch; loss tiles run as epilogues on the
// blocks scheduled JUST AFTER each image's producers (freshness + residency
// matched; no dedicated waiters).
//   original, enhanced: [32,3,512,512] f32
//   p = avg_pool4(mean_c(orig)) - avg_pool4(mean_c(enh))   [32,128,128]
//   loss[i,j] = sum_dirs (p[i,j] - p[nbr])^2, zero-padded  -> [32,1,128,128]
//
// Mapping: producers of image m are bids 64m..64m+63 (finish ~in bid order).
//   blocks 64(m+1)+r, r<16      -> tile r of image m      (m = 0..30)
//   blocks 64*31+r,   r in 48..63 -> tile r-48 of image 31 (self-group tail)
// Executor frees right when its tile's image completes => ~zero spin, and
// the scratch it reads was written within ~1us => L2-hot (fixes R16's
// cold-scratch tail; fixes R14's idle-resident consumers).
// Waits target lower (or same-group trailing) bids; <=512 waiters << chip
// capacity => forward progress. Counters self-reset => replay-deterministic.

#define B 32
#define HP 128
#define WP 128
#define NPOOL (B * HP * WP)   // 524288
#define HIN 512
#define WIN 512
#define CH_STRIDE (HIN * WIN)          // 262144
#define IMG_STRIDE (3 * CH_STRIDE)     // 786432
#define THREADS 256
#define POOL_BLOCKS (NPOOL / THREADS)      // 2048 (64 per image)
#define LOSS_TILES (NPOOL / 4 / THREADS)   // 512 tiles (16 per image)
#define PROD_PER_IMG (POOL_BLOCKS / B)     // 64

__device__ float g_pooled[NPOOL];            // 2 MB scratch
__device__ unsigned int g_img_done[B];       // per-image producer counters
__device__ unsigned int g_tiles_done;        // completed loss tiles (reset)

__device__ __forceinline__ float sq(float x) { return x * x; }

__global__ __launch_bounds__(THREADS, 8)
void scl_nextimg_kernel(const float* __restrict__ orig,
                        const float* __restrict__ enh,
                        float* __restrict__ out) {
    // ================= Production: every block streams 1/2048 =============
    int idx = blockIdx.x * THREADS + threadIdx.x;

    int j = idx & (WP - 1);
    int i = (idx >> 7) & (HP - 1);
    int b = idx >> 14;

    int base0 = b * IMG_STRIDE + (i * 4) * WIN + (j * 4);

    float s = 0.0f;
#pragma unroll
    for (int c = 0; c < 3; ++c) {
        int base = base0 + c * CH_STRIDE;
#pragma unroll
        for (int r = 0; r < 4; ++r) {
            float4 ov = __ldcs(reinterpret_cast<const float4*>(orig + base + r * WIN));
            float4 ev = __ldcs(reinterpret_cast<const float4*>(enh  + base + r * WIN));
            s += (ov.x - ev.x) + (ov.y - ev.y) + (ov.z - ev.z) + (ov.w - ev.w);
        }
    }
    g_pooled[idx] = s * (1.0f / 48.0f);   // /3 channels, /16 pool

    __syncthreads();
    if (threadIdx.x == 0) {
        __threadfence();                  // release this block's scratch
        atomicAdd(&g_img_done[b], 1u);
    }

    // ================= Epilogue: tile assignment ==========================
    // Executor selection (see header): tile of the PREVIOUS image region.
    const int m  = blockIdx.x >> 6;       // this block's image (= b)
    const int r  = blockIdx.x & 63;
    int tile = -1;
    if (m >= 1 && r < 16)                 tile = (m - 1) * 16 + r;      // images 0..30
    else if (m == B - 1 && r >= 48)       tile = (B - 1) * 16 + (r - 48); // image 31

    if (tile >= 0) {
        int timg = tile >> 4;             // tile's image

        if (threadIdx.x == 0) {
            // Usually already satisfied: executor bids trail the producers.
            while (*(volatile unsigned int*)&g_img_done[timg] < PROD_PER_IMG) { }
            __threadfence();              // acquire that image's scratch
        }
        __syncthreads();

        int q   = tile * THREADS + threadIdx.x; // quad index, 0..NPOOL/4-1
        int j4  = (q & 31) << 2;                // first j of the 4-wide quad
        int row = q >> 5;                       // b*128 + i
        int ii  = row & (HP - 1);
        int base = (row << 7) + j4;

        const float4* p4 = reinterpret_cast<const float4*>(g_pooled);
        float4 c  = p4[base >> 2];
        float4 up = (ii > 0)      ? p4[(base - WP) >> 2] : make_float4(0.f, 0.f, 0.f, 0.f);
        float4 dn = (ii < HP - 1) ? p4[(base + WP) >> 2] : make_float4(0.f, 0.f, 0.f, 0.f);
        float left  = (j4 > 0)      ? g_pooled[base - 1] : 0.f;
        float right = (j4 < WP - 4) ? g_pooled[base + 4] : 0.f;

        float4 o;
        o.x = sq(c.x - left) + sq(c.x - c.y)   + sq(c.x - up.x) + sq(c.x - dn.x);
        o.y = sq(c.y - c.x)  + sq(c.y - c.z)   + sq(c.y - up.y) + sq(c.y - dn.y);
        o.z = sq(c.z - c.y)  + sq(c.z - c.w)   + sq(c.z - up.z) + sq(c.z - dn.z);
        o.w = sq(c.w - c.z)  + sq(c.w - right) + sq(c.w - up.w) + sq(c.w - dn.w);

        reinterpret_cast<float4*>(out)[base >> 2] = o;

        // -------- Reset shared state for the next graph replay --------
        __syncthreads();
        if (threadIdx.x == 0) {
            unsigned int old = atomicAdd(&g_tiles_done, 1u);
            if (old == LOSS_TILES - 1) {  // last tile => all counters maxed
#pragma unroll
                for (int k = 0; k < B; ++k)
                    atomicExch(&g_img_done[k], 0u);
                atomicExch(&g_tiles_done, 0u);
            }
        }
    }
}

extern "C" void kernel_launch(void* const* d_in, const int* in_sizes, int n_in,
                              void* d_out, int out_size) {
    const float* orig = (const float*)d_in[0];
    const float* enh  = (const float*)d_in[1];
    float* out = (float*)d_out;

    scl_nextimg_kernel<<<POOL_BLOCKS, THREADS>>>(orig, enh, out);
}